// round 12
// baseline (speedup 1.0000x reference)
#include <cuda_runtime.h>
#include <cuda_bf16.h>
#include <cstdint>

// ---------------------------------------------------------------------------
// GCNEncoder: 2-layer GCN.
//   h1 = relu( Dinv (A+I) Dinv (x @ W1) + b1 )
//   out =      Dinv (A+I) Dinv (h1 @ W2) + b2
// N = 100000, E = 1600000, CH = 128.
// R12: bf16x3 mma.sync m16n8k16 GEMM with ldmatrix fragment loads.
// M-tile=64 (2 CTAs/SM), x-split fused into GEMM1 A-load, A hi/lo images
// row-major [node][128]. CSR pull gather.
// (tcgen05 unavailable: harness compiles PTX at sm_100, no 'a'.)
// ---------------------------------------------------------------------------

#define MAX_N 100000
#define AROWS 100096
#define MAX_E 1600000
#define CH 128

__device__ alignas(16) float g_h[(size_t)MAX_N * CH];
__device__ alignas(16) __nv_bfloat16 g_Ahi[(size_t)AROWS * CH];
__device__ alignas(16) __nv_bfloat16 g_Alo[(size_t)AROWS * CH];
__device__ alignas(16) __nv_bfloat16 g_W1hi[CH * CH];   // [n][k] transposed
__device__ alignas(16) __nv_bfloat16 g_W1lo[CH * CH];
__device__ alignas(16) __nv_bfloat16 g_W2hi[CH * CH];
__device__ alignas(16) __nv_bfloat16 g_W2lo[CH * CH];
__device__ float g_dinv[MAX_N];
__device__ int   g_deg[MAX_N];
__device__ int   g_row[MAX_N];
__device__ int   g_cur[MAX_N];
__device__ int   g_idx[2 * MAX_E];
__device__ int2  g_csr[MAX_E];
__device__ unsigned int g_or_hi;
__device__ unsigned int g_alloc;

// ---------------------------------------------------------------------------
// (1) init + dtype detection. int64 indices in [0,N) have zero high words.
// (Detection window bounded to first 2048 words: safe under either dtype.)
// ---------------------------------------------------------------------------
__global__ void init_detect_kernel(const unsigned int* __restrict__ w,
                                   int nwords, int n) {
    int i = blockIdx.x * blockDim.x + threadIdx.x;
    if (i < n) g_deg[i] = 0;
    if (i == 0) { g_alloc = 0u; }
    if (blockIdx.x == 0) {
        unsigned int v = 0;
        for (int j = threadIdx.x; j < 1024; j += blockDim.x) {
            int idx = 2 * j + 1;
            if (idx < nwords) v |= w[idx];
        }
        for (int off = 16; off > 0; off >>= 1)
            v |= __shfl_down_sync(0xFFFFFFFFu, v, off);
        __shared__ unsigned int sv[8];
        if ((threadIdx.x & 31) == 0) sv[threadIdx.x >> 5] = v;
        __syncthreads();
        if (threadIdx.x == 0) {
            unsigned int r = 0;
            for (int wz = 0; wz < (int)(blockDim.x >> 5); wz++) r |= sv[wz];
            g_or_hi = r;
        }
    }
}

// (2) convert indices to int32 + count in-degrees (dst half).
__global__ void convert_kernel(const void* __restrict__ ei, int E) {
    int i = blockIdx.x * blockDim.x + threadIdx.x;
    if (i >= 2 * E) return;
    int v;
    if (g_or_hi == 0u) v = (int)((const long long*)ei)[i];
    else               v = ((const int*)ei)[i];
    g_idx[i] = v;
    if (i >= E) atomicAdd(&g_deg[v], 1);
}

// ---------------------------------------------------------------------------
// (3) Split W1/W2 to bf16 hi/lo as B[n][k] (block 0 = W1, block 1 = W2).
// ---------------------------------------------------------------------------
__global__ void __launch_bounds__(256)
split_w_kernel(const float* __restrict__ W1, const float* __restrict__ W2) {
    int b = blockIdx.x;
    int tid = threadIdx.x;
    const float* W = (b == 0) ? W1 : W2;
    __nv_bfloat16* dh = (b == 0) ? g_W1hi : g_W2hi;
    __nv_bfloat16* dl = (b == 0) ? g_W1lo : g_W2lo;
#pragma unroll
    for (int i = 0; i < 8; i++) {
        int chunk = tid + i * 256;        // 0..2047
        int k = chunk >> 4;
        int n8 = (chunk & 15) * 8;
        const float4* src = (const float4*)(W + (size_t)k * CH + n8);
        float4 v0 = src[0], v1 = src[1];
        float vv[8] = {v0.x, v0.y, v0.z, v0.w, v1.x, v1.y, v1.z, v1.w};
#pragma unroll
        for (int j = 0; j < 8; j++) {
            __nv_bfloat16 h = __float2bfloat16(vv[j]);
            __nv_bfloat16 l = __float2bfloat16(vv[j] - __bfloat162float(h));
            dh[(n8 + j) * CH + k] = h;    // B[n][k] = W[k][n]
            dl[(n8 + j) * CH + k] = l;
        }
    }
}

// ---------------------------------------------------------------------------
// (5) dinv + CSR row allocation (block scan + atomic base).
// ---------------------------------------------------------------------------
__global__ void __launch_bounds__(256)
dinv_alloc_kernel(int n) {
    int i = blockIdx.x * 256 + threadIdx.x;
    int lane = threadIdx.x & 31;
    int wid = threadIdx.x >> 5;
    int d = (i < n) ? g_deg[i] : 0;
    if (i < n) g_dinv[i] = rsqrtf((float)d + 1.0f);

    int v = d;
#pragma unroll
    for (int off = 1; off < 32; off <<= 1) {
        int t = __shfl_up_sync(0xFFFFFFFFu, v, off);
        if (lane >= off) v += t;
    }
    __shared__ int wsum[8];
    __shared__ int woff[8];
    __shared__ int base;
    if (lane == 31) wsum[wid] = v;
    __syncthreads();
    if (threadIdx.x == 0) {
        int run = 0;
#pragma unroll
        for (int w = 0; w < 8; w++) { woff[w] = run; run += wsum[w]; }
        base = (int)atomicAdd(&g_alloc, (unsigned int)run);
    }
    __syncthreads();
    if (i < n) {
        int start = base + woff[wid] + (v - d);
        g_row[i] = start;
        g_cur[i] = start;
    }
}

// (6) Fill CSR: (src, coef) per edge, grouped by dst.
__global__ void csr_fill_kernel(int E) {
    int e = blockIdx.x * blockDim.x + threadIdx.x;
    if (e >= E) return;
    int s = g_idx[e];
    int d = g_idx[E + e];
    float coef = g_dinv[s] * g_dinv[d];
    int pos = atomicAdd(&g_cur[d], 1);
    g_csr[pos] = make_int2(s, __float_as_int(coef));
}

// ---------------------------------------------------------------------------
// (4,8) GEMM: C[64-row tile][128] = A @ B^T via mma.sync m16n8k16 bf16,
// 3-term compensation, ldmatrix fragment loads.
// 256 threads, 8 warps as 4x2 -> 16x64 per warp. Whole K resident in smem.
// ---------------------------------------------------------------------------
__device__ __forceinline__ void mma_bf16(float* c, const unsigned* a, const unsigned* b) {
    asm volatile(
        "mma.sync.aligned.m16n8k16.row.col.f32.bf16.bf16.f32 "
        "{%0,%1,%2,%3}, {%4,%5,%6,%7}, {%8,%9}, {%0,%1,%2,%3};"
        : "+f"(c[0]), "+f"(c[1]), "+f"(c[2]), "+f"(c[3])
        : "r"(a[0]), "r"(a[1]), "r"(a[2]), "r"(a[3]), "r"(b[0]), "r"(b[1]));
}
__device__ __forceinline__ void ldsm_x4(unsigned* r, unsigned addr) {
    asm volatile("ldmatrix.sync.aligned.m8n8.x4.shared.b16 {%0,%1,%2,%3}, [%4];"
                 : "=r"(r[0]), "=r"(r[1]), "=r"(r[2]), "=r"(r[3]) : "r"(addr));
}
__device__ __forceinline__ void cpa16p(unsigned dst, const void* src, bool p) {
    int sz = p ? 16 : 0;
    asm volatile("cp.async.cg.shared.global [%0], [%1], 16, %2;"
                 :: "r"(dst), "l"(src), "r"(sz) : "memory");
}
#define CP_COMMIT() asm volatile("cp.async.commit_group;" ::: "memory")
#define CP_WAIT0()  asm volatile("cp.async.wait_group 0;" ::: "memory")

#define SROW_B 272                     // smem row stride bytes (136 bf16)
#define A_B  (64 * SROW_B)             // 17408 B per A array
#define W_B  (128 * SROW_B)            // 34816 B per W array
#define SM_AH 0
#define SM_AL A_B
#define SM_WH (2 * A_B)
#define SM_WL (2 * A_B + W_B)
#define SMEM_T (2 * A_B + 2 * W_B)     // 104448 B

template <int LAYER>
__global__ void __launch_bounds__(256)
gemm_bf16_kernel(const float* __restrict__ X, float* __restrict__ C, int n) {
    extern __shared__ char smem[];
    const int tid = threadIdx.x;
    const int lane = tid & 31;
    const int wid = tid >> 5;
    const int block_row = blockIdx.x * 64;
    const int wm = (wid & 3) * 16;
    const int wn = (wid >> 2) * 64;
    const int gid = lane >> 2;
    const int tig = lane & 3;

    unsigned sb;
    asm("{ .reg .u64 t; cvta.to.shared.u64 t, %1; cvt.u32.u64 %0, t; }"
        : "=r"(sb) : "l"(smem));

    // W hi/lo via cp.async (128 rows x 256 B each).
    const char* wh = (const char*)(LAYER == 1 ? g_W1hi : g_W2hi);
    const char* wl = (const char*)(LAYER == 1 ? g_W1lo : g_W2lo);
#pragma unroll
    for (int i = 0; i < 8; i++) {
        int chunk = tid + i * 256;
        int r = chunk >> 4;
        int cB = (chunk & 15) * 16;
        cpa16p(sb + SM_WH + r * SROW_B + cB, wh + r * 256 + cB, true);
        cpa16p(sb + SM_WL + r * SROW_B + cB, wl + r * 256 + cB, true);
    }

    if (LAYER == 1) {
        // A: load fp32 rows of x, split to bf16 hi/lo in registers, STS.
        __nv_bfloat16* sah = (__nv_bfloat16*)(smem + SM_AH);
        __nv_bfloat16* sal = (__nv_bfloat16*)(smem + SM_AL);
#pragma unroll
        for (int i = 0; i < 4; i++) {
            int chunk = tid + i * 256;
            int r = chunk >> 4;
            int c8 = (chunk & 15) * 8;
            int gr = block_row + r;
            float4 v0 = make_float4(0.f, 0.f, 0.f, 0.f), v1 = v0;
            if (gr < n) {
                const float4* src = (const float4*)(X + (size_t)gr * CH + c8);
                v0 = src[0];
                v1 = src[1];
            }
            float vv[8] = {v0.x, v0.y, v0.z, v0.w, v1.x, v1.y, v1.z, v1.w};
            __nv_bfloat16 hi[8], lo[8];
#pragma unroll
            for (int j = 0; j < 8; j++) {
                hi[j] = __float2bfloat16(vv[j]);
                lo[j] = __float2bfloat16(vv[j] - __bfloat162float(hi[j]));
            }
            *(uint4*)(sah + r * 136 + c8) = *(uint4*)hi;
            *(uint4*)(sal + r * 136 + c8) = *(uint4*)lo;
        }
    } else {
        // A hi/lo via cp.async from row-major images (64 rows x 256 B).
#pragma unroll
        for (int i = 0; i < 4; i++) {
            int chunk = tid + i * 256;
            int r = chunk >> 4;
            int cB = (chunk & 15) * 16;
            int gr = block_row + r;
            bool ok = gr < n;
            int srow = ok ? gr : (n - 1);
            cpa16p(sb + SM_AH + r * SROW_B + cB, (const char*)g_Ahi + (size_t)srow * 256 + cB, ok);
            cpa16p(sb + SM_AL + r * SROW_B + cB, (const char*)g_Alo + (size_t)srow * 256 + cB, ok);
        }
    }
    CP_COMMIT();
    CP_WAIT0();
    __syncthreads();

    // ldmatrix per-lane base addresses.
    // A x4: lanes 0-15 -> rows wm+0..15 k-lo, lanes 16-31 -> same rows k-hi
    //   => {a0,a1,a2,a3} canonical m16n8k16 A fragment.
    const unsigned a_off = (unsigned)((wm + (lane & 15)) * SROW_B + (lane >> 4) * 16);
    // B x4 per nt-pair p: m0 = rows p*16..+7 k-lo, m1 = k-hi,
    //   m2 = rows p*16+8..+15 k-lo, m3 = k-hi => {b0,b1} for nt=2p, 2p+1.
    const unsigned b_off = (unsigned)((wn + (lane & 7) + ((lane >> 4) << 3)) * SROW_B
                                      + ((lane >> 3) & 1) * 16);

    float acc[8][4];
#pragma unroll
    for (int nt = 0; nt < 8; nt++)
#pragma unroll
        for (int r = 0; r < 4; r++) acc[nt][r] = 0.0f;

#pragma unroll
    for (int ks = 0; ks < 8; ks++) {
        const unsigned kB = ks * 32;
        unsigned ah[4], al[4];
        ldsm_x4(ah, sb + SM_AH + a_off + kB);
        ldsm_x4(al, sb + SM_AL + a_off + kB);
#pragma unroll
        for (int p = 0; p < 4; p++) {
            unsigned bh[4], bl[4];
            ldsm_x4(bh, sb + SM_WH + b_off + p * 16 * SROW_B + kB);
            ldsm_x4(bl, sb + SM_WL + b_off + p * 16 * SROW_B + kB);
            mma_bf16(acc[2 * p],     ah, bh);      // hi*hi  (nt = 2p)
            mma_bf16(acc[2 * p],     ah, bl);      // hi*lo
            mma_bf16(acc[2 * p],     al, bh);      // lo*hi
            mma_bf16(acc[2 * p + 1], ah, bh + 2);  // nt = 2p+1
            mma_bf16(acc[2 * p + 1], ah, bl + 2);
            mma_bf16(acc[2 * p + 1], al, bh + 2);
        }
    }

    // Epilogue: c0,c1 -> (row, 2tig/2tig+1); c2,c3 -> row+8.
#pragma unroll
    for (int nt = 0; nt < 8; nt++) {
        int r0 = block_row + wm + gid;
        int cb = wn + nt * 8 + 2 * tig;
        if (r0 < n)
            *(float2*)(C + (size_t)r0 * CH + cb) = make_float2(acc[nt][0], acc[nt][1]);
        if (r0 + 8 < n)
            *(float2*)(C + (size_t)(r0 + 8) * CH + cb) = make_float2(acc[nt][2], acc[nt][3]);
    }
}

// ---------------------------------------------------------------------------
// (7,9) Pull aggregation: one warp per node, register accumulation.
// SPLIT=true: relu + write bf16 hi/lo rows (feeds GEMM2).
// SPLIT=false: write fp32 rows (final output).
// ---------------------------------------------------------------------------
template <bool SPLIT>
__global__ void __launch_bounds__(256)
gather_kernel(const float* __restrict__ h, const float* __restrict__ b,
              float* __restrict__ out, int n) {
    int node = (blockIdx.x * blockDim.x + threadIdx.x) >> 5;
    int lane = threadIdx.x & 31;
    if (node >= n) return;

    int start = g_row[node];
    int deg = g_deg[node];
    float di = g_dinv[node];
    float sl = di * di;

    float4 hv = ((const float4*)(h + (size_t)node * CH))[lane];
    float4 bv = ((const float4*)b)[lane];
    float4 acc;
    acc.x = fmaf(hv.x, sl, bv.x);
    acc.y = fmaf(hv.y, sl, bv.y);
    acc.z = fmaf(hv.z, sl, bv.z);
    acc.w = fmaf(hv.w, sl, bv.w);

    for (int j0 = 0; j0 < deg; j0 += 32) {
        int nn = min(32, deg - j0);
        int2 e = make_int2(0, 0);
        if (lane < nn) e = g_csr[start + j0 + lane];
#pragma unroll 8
        for (int k = 0; k < nn; k++) {
            int s = __shfl_sync(0xFFFFFFFFu, e.x, k);
            float c = __int_as_float(__shfl_sync(0xFFFFFFFFu, e.y, k));
            float4 v = ((const float4*)(h + (size_t)s * CH))[lane];
            acc.x = fmaf(v.x, c, acc.x);
            acc.y = fmaf(v.y, c, acc.y);
            acc.z = fmaf(v.z, c, acc.z);
            acc.w = fmaf(v.w, c, acc.w);
        }
    }

    if (SPLIT) {
        float vv[4] = {fmaxf(acc.x, 0.f), fmaxf(acc.y, 0.f),
                       fmaxf(acc.z, 0.f), fmaxf(acc.w, 0.f)};
        __nv_bfloat16 hi[4], lo[4];
#pragma unroll
        for (int j = 0; j < 4; j++) {
            hi[j] = __float2bfloat16(vv[j]);
            lo[j] = __float2bfloat16(vv[j] - __bfloat162float(hi[j]));
        }
        size_t off = (size_t)node * CH + lane * 4;
        *(uint2*)(g_Ahi + off) = *(uint2*)hi;
        *(uint2*)(g_Alo + off) = *(uint2*)lo;
    } else {
        ((float4*)(out + (size_t)node * CH))[lane] = acc;
    }
}

// ---------------------------------------------------------------------------
// Launch. Slot 4 (ncu-profiled) = gemm layer 1.
// ---------------------------------------------------------------------------
extern "C" void kernel_launch(void* const* d_in, const int* in_sizes, int n_in,
                              void* d_out, int out_size) {
    const float* x  = (const float*)d_in[0];
    const void*  ei = d_in[1];
    const float* W1 = (const float*)d_in[2];
    const float* b1 = (const float*)d_in[3];
    const float* W2 = (const float*)d_in[4];
    const float* b2 = (const float*)d_in[5];
    float*       out = (float*)d_out;

    const int N = in_sizes[0] / CH;
    const int E = in_sizes[1] / 2;
    const int nt64 = (N + 63) / 64;

    float* hp = nullptr;
    cudaGetSymbolAddress((void**)&hp, g_h);

    cudaFuncSetAttribute(gemm_bf16_kernel<1>,
                         cudaFuncAttributeMaxDynamicSharedMemorySize, SMEM_T);
    cudaFuncSetAttribute(gemm_bf16_kernel<2>,
                         cudaFuncAttributeMaxDynamicSharedMemorySize, SMEM_T);

    const int T = 256;
    const int edge_grid = (E + T - 1) / T;
    const int node_grid = (N + T - 1) / T;
    const int conv_grid = (2 * E + T - 1) / T;
    const int warp_grid = (N * 32 + T - 1) / T;

    init_detect_kernel<<<node_grid, T>>>((const unsigned int*)ei, 2 * E, N); // 1
    convert_kernel<<<conv_grid, T>>>(ei, E);                                 // 2
    split_w_kernel<<<2, T>>>(W1, W2);                                        // 3
    gemm_bf16_kernel<1><<<nt64, T, SMEM_T>>>(x, hp, N);                      // 4 (profiled)
    dinv_alloc_kernel<<<node_grid, T>>>(N);                                  // 5
    csr_fill_kernel<<<edge_grid, T>>>(E);                                    // 6
    gather_kernel<true><<<warp_grid, T>>>(hp, b1, nullptr, N);               // 7
    gemm_bf16_kernel<2><<<nt64, T, SMEM_T>>>(nullptr, hp, N);                // 8
    gather_kernel<false><<<warp_grid, T>>>(hp, b2, out, N);                  // 9
}

// round 13
// speedup vs baseline: 1.0233x; 1.0233x over previous
#include <cuda_runtime.h>
#include <cuda_bf16.h>
#include <cstdint>

// ---------------------------------------------------------------------------
// GCNEncoder: 2-layer GCN.
//   h1 = relu( Dinv (A+I) Dinv (x @ W1) + b1 )
//   out =      Dinv (A+I) Dinv (h1 @ W2) + b2
// N = 100000, E = 1600000, CH = 128.
// R13: persistent bf16x3 mma.sync GEMM — W resident in smem across all
// M-tiles (loaded once per CTA), A double-buffered (L2) / reg-prefetched
// (L1, fp32 split fused). CSR pull gather unchanged.
// (tcgen05 unavailable: harness compiles PTX at sm_100, no 'a'.)
// ---------------------------------------------------------------------------

#define MAX_N 100000
#define AROWS 100096                  // 782 * 128, padded
#define MAX_E 1600000
#define CH 128
#define PGRID 148                     // persistent grid (1 CTA/SM)

__device__ alignas(16) float g_h[(size_t)MAX_N * CH];
__device__ alignas(16) __nv_bfloat16 g_Ahi[(size_t)AROWS * CH];
__device__ alignas(16) __nv_bfloat16 g_Alo[(size_t)AROWS * CH];
__device__ alignas(16) __nv_bfloat16 g_W1hi[CH * CH];   // [n][k] transposed
__device__ alignas(16) __nv_bfloat16 g_W1lo[CH * CH];
__device__ alignas(16) __nv_bfloat16 g_W2hi[CH * CH];
__device__ alignas(16) __nv_bfloat16 g_W2lo[CH * CH];
__device__ float g_dinv[MAX_N];
__device__ int   g_deg[MAX_N];
__device__ int   g_row[MAX_N];
__device__ int   g_cur[MAX_N];
__device__ int   g_idx[2 * MAX_E];
__device__ int2  g_csr[MAX_E];
__device__ unsigned int g_or_hi;
__device__ unsigned int g_alloc;

// ---------------------------------------------------------------------------
// (1) init + dtype detection. int64 indices in [0,N) have zero high words.
// ---------------------------------------------------------------------------
__global__ void init_detect_kernel(const unsigned int* __restrict__ w,
                                   int nwords, int n) {
    int i = blockIdx.x * blockDim.x + threadIdx.x;
    if (i < n) g_deg[i] = 0;
    if (i == 0) { g_alloc = 0u; }
    if (blockIdx.x == 0) {
        unsigned int v = 0;
        for (int j = threadIdx.x; j < 1024; j += blockDim.x) {
            int idx = 2 * j + 1;
            if (idx < nwords) v |= w[idx];
        }
        for (int off = 16; off > 0; off >>= 1)
            v |= __shfl_down_sync(0xFFFFFFFFu, v, off);
        __shared__ unsigned int sv[8];
        if ((threadIdx.x & 31) == 0) sv[threadIdx.x >> 5] = v;
        __syncthreads();
        if (threadIdx.x == 0) {
            unsigned int r = 0;
            for (int wz = 0; wz < (int)(blockDim.x >> 5); wz++) r |= sv[wz];
            g_or_hi = r;
        }
    }
}

// (2) convert indices to int32 + count in-degrees (dst half).
__global__ void convert_kernel(const void* __restrict__ ei, int E) {
    int i = blockIdx.x * blockDim.x + threadIdx.x;
    if (i >= 2 * E) return;
    int v;
    if (g_or_hi == 0u) v = (int)((const long long*)ei)[i];
    else               v = ((const int*)ei)[i];
    g_idx[i] = v;
    if (i >= E) atomicAdd(&g_deg[v], 1);
}

// ---------------------------------------------------------------------------
// (3) Split W1/W2 to bf16 hi/lo as B[n][k] (block 0 = W1, block 1 = W2).
// ---------------------------------------------------------------------------
__global__ void __launch_bounds__(256)
split_w_kernel(const float* __restrict__ W1, const float* __restrict__ W2) {
    int b = blockIdx.x;
    int tid = threadIdx.x;
    const float* W = (b == 0) ? W1 : W2;
    __nv_bfloat16* dh = (b == 0) ? g_W1hi : g_W2hi;
    __nv_bfloat16* dl = (b == 0) ? g_W1lo : g_W2lo;
#pragma unroll
    for (int i = 0; i < 8; i++) {
        int chunk = tid + i * 256;        // 0..2047
        int k = chunk >> 4;
        int n8 = (chunk & 15) * 8;
        const float4* src = (const float4*)(W + (size_t)k * CH + n8);
        float4 v0 = src[0], v1 = src[1];
        float vv[8] = {v0.x, v0.y, v0.z, v0.w, v1.x, v1.y, v1.z, v1.w};
#pragma unroll
        for (int j = 0; j < 8; j++) {
            __nv_bfloat16 h = __float2bfloat16(vv[j]);
            __nv_bfloat16 l = __float2bfloat16(vv[j] - __bfloat162float(h));
            dh[(n8 + j) * CH + k] = h;    // B[n][k] = W[k][n]
            dl[(n8 + j) * CH + k] = l;
        }
    }
}

// ---------------------------------------------------------------------------
// (5) dinv + CSR row allocation (block scan + atomic base).
// ---------------------------------------------------------------------------
__global__ void __launch_bounds__(256)
dinv_alloc_kernel(int n) {
    int i = blockIdx.x * 256 + threadIdx.x;
    int lane = threadIdx.x & 31;
    int wid = threadIdx.x >> 5;
    int d = (i < n) ? g_deg[i] : 0;
    if (i < n) g_dinv[i] = rsqrtf((float)d + 1.0f);

    int v = d;
#pragma unroll
    for (int off = 1; off < 32; off <<= 1) {
        int t = __shfl_up_sync(0xFFFFFFFFu, v, off);
        if (lane >= off) v += t;
    }
    __shared__ int wsum[8];
    __shared__ int woff[8];
    __shared__ int base;
    if (lane == 31) wsum[wid] = v;
    __syncthreads();
    if (threadIdx.x == 0) {
        int run = 0;
#pragma unroll
        for (int w = 0; w < 8; w++) { woff[w] = run; run += wsum[w]; }
        base = (int)atomicAdd(&g_alloc, (unsigned int)run);
    }
    __syncthreads();
    if (i < n) {
        int start = base + woff[wid] + (v - d);
        g_row[i] = start;
        g_cur[i] = start;
    }
}

// (6) Fill CSR: (src, coef) per edge, grouped by dst.
__global__ void csr_fill_kernel(int E) {
    int e = blockIdx.x * blockDim.x + threadIdx.x;
    if (e >= E) return;
    int s = g_idx[e];
    int d = g_idx[E + e];
    float coef = g_dinv[s] * g_dinv[d];
    int pos = atomicAdd(&g_cur[d], 1);
    g_csr[pos] = make_int2(s, __float_as_int(coef));
}

// ---------------------------------------------------------------------------
// (4,8) Persistent GEMM: C = A @ B^T, bf16x3, m16n8k16 + ldmatrix.
// 148 CTAs x 512 threads (16 warps as 4x4 -> 32x32/warp), M-tile 128.
// W hi/lo resident in smem for all tiles.
// LAYER 1: A = fp32 x rows, split in-kernel, next tile prefetched to regs.
// LAYER 2: A hi/lo cp.async double-buffered from row-major images.
// ---------------------------------------------------------------------------
__device__ __forceinline__ void mma_bf16(float* c, const unsigned* a, const unsigned* b) {
    asm volatile(
        "mma.sync.aligned.m16n8k16.row.col.f32.bf16.bf16.f32 "
        "{%0,%1,%2,%3}, {%4,%5,%6,%7}, {%8,%9}, {%0,%1,%2,%3};"
        : "+f"(c[0]), "+f"(c[1]), "+f"(c[2]), "+f"(c[3])
        : "r"(a[0]), "r"(a[1]), "r"(a[2]), "r"(a[3]), "r"(b[0]), "r"(b[1]));
}
__device__ __forceinline__ void ldsm_x4(unsigned* r, unsigned addr) {
    asm volatile("ldmatrix.sync.aligned.m8n8.x4.shared.b16 {%0,%1,%2,%3}, [%4];"
                 : "=r"(r[0]), "=r"(r[1]), "=r"(r[2]), "=r"(r[3]) : "r"(addr));
}
__device__ __forceinline__ void cpa16(unsigned dst, const void* src) {
    asm volatile("cp.async.cg.shared.global [%0], [%1], 16;"
                 :: "r"(dst), "l"(src) : "memory");
}
#define CP_COMMIT() asm volatile("cp.async.commit_group;" ::: "memory")
#define CP_WAIT0()  asm volatile("cp.async.wait_group 0;" ::: "memory")

#define SROW_B 272                     // smem row stride bytes (136 bf16)
#define ARR_B  (128 * SROW_B)          // 34816 B: one 128-row bf16 array
#define SM_WH  0
#define SM_WL  ARR_B
#define SM_A0  (2 * ARR_B)             // A stage base; stage = SM_A0 + s*2*ARR_B
#define SMEM_L1 (4 * ARR_B)            // W(2) + A stage(2)          = 139264
#define SMEM_L2 (6 * ARR_B)            // W(2) + A stages(4)         = 208896

template <int LAYER>
__global__ void __launch_bounds__(512)
gemm_bf16_kernel(const float* __restrict__ X, float* __restrict__ C,
                 int n, int ntiles) {
    extern __shared__ char smem[];
    const int tid = threadIdx.x;
    const int lane = tid & 31;
    const int wid = tid >> 5;
    const int wm = (wid & 3) * 32;       // 2 m16 tiles
    const int wn = (wid >> 2) * 32;      // 4 n8 tiles
    const int gid = lane >> 2;
    const int tig = lane & 3;

    unsigned sb;
    asm("{ .reg .u64 t; cvta.to.shared.u64 t, %1; cvt.u32.u64 %0, t; }"
        : "=r"(sb) : "l"(smem));

    // ---- Load W hi/lo once (resident for all tiles). 4 chunks/thr/array.
    {
        const char* wh = (const char*)(LAYER == 1 ? g_W1hi : g_W2hi);
        const char* wl = (const char*)(LAYER == 1 ? g_W1lo : g_W2lo);
#pragma unroll
        for (int i = 0; i < 4; i++) {
            int chunk = tid + i * 512;      // 0..2047
            int r = chunk >> 4;
            int cB = (chunk & 15) * 16;
            cpa16(sb + SM_WH + r * SROW_B + cB, wh + r * 256 + cB);
            cpa16(sb + SM_WL + r * SROW_B + cB, wl + r * 256 + cB);
        }
        CP_COMMIT();
    }

    // ldmatrix per-lane base offsets (within an A/W array).
    const unsigned a_off = (unsigned)((wm + (lane & 15)) * SROW_B + (lane >> 4) * 16);
    const unsigned b_off = (unsigned)((wn + (lane & 7) + ((lane >> 4) << 3)) * SROW_B
                                      + ((lane >> 3) & 1) * 16);

    // L1 prefetch registers: 8 float4 chunks (rows r=chunk>>5, col (chunk&31)*4).
    float4 pf[8];
    auto load_x = [&](int tile) {
#pragma unroll
        for (int i = 0; i < 8; i++) {
            int chunk = tid + i * 512;      // 0..4095
            int r = chunk >> 5;
            int c4 = (chunk & 31) * 4;
            int gr = tile * 128 + r;
            pf[i] = (gr < n) ? *(const float4*)(X + (size_t)gr * CH + c4)
                             : make_float4(0.f, 0.f, 0.f, 0.f);
        }
    };
    auto sts_x = [&](unsigned stage) {
        __nv_bfloat16* sah = (__nv_bfloat16*)(smem + stage);
        __nv_bfloat16* sal = (__nv_bfloat16*)(smem + stage + ARR_B);
#pragma unroll
        for (int i = 0; i < 8; i++) {
            int chunk = tid + i * 512;
            int r = chunk >> 5;
            int c4 = (chunk & 31) * 4;
            float vv[4] = {pf[i].x, pf[i].y, pf[i].z, pf[i].w};
            __nv_bfloat16 hi[4], lo[4];
#pragma unroll
            for (int j = 0; j < 4; j++) {
                hi[j] = __float2bfloat16(vv[j]);
                lo[j] = __float2bfloat16(vv[j] - __bfloat162float(hi[j]));
            }
            *(uint2*)(sah + r * 136 + c4) = *(uint2*)hi;
            *(uint2*)(sal + r * 136 + c4) = *(uint2*)lo;
        }
    };
    auto issue_a = [&](int tile, unsigned stage) {   // L2: 4 chunks/thr/array
#pragma unroll
        for (int i = 0; i < 4; i++) {
            int chunk = tid + i * 512;      // 0..2047
            int r = chunk >> 4;
            int cB = (chunk & 15) * 16;
            size_t g = (size_t)(tile * 128 + r) * 256 + cB;   // rows < AROWS
            cpa16(sb + stage + r * SROW_B + cB, (const char*)g_Ahi + g);
            cpa16(sb + stage + ARR_B + r * SROW_B + cB, (const char*)g_Alo + g);
        }
        CP_COMMIT();
    };

    auto compute_store = [&](unsigned stage, int tile) {
        float acc[2][4][4];
#pragma unroll
        for (int mt = 0; mt < 2; mt++)
#pragma unroll
            for (int nt = 0; nt < 4; nt++)
#pragma unroll
                for (int r = 0; r < 4; r++) acc[mt][nt][r] = 0.0f;

#pragma unroll
        for (int ks = 0; ks < 8; ks++) {
            const unsigned kB = ks * 32;
            unsigned ah[2][4], al[2][4];
#pragma unroll
            for (int mt = 0; mt < 2; mt++) {
                ldsm_x4(ah[mt], sb + stage + a_off + mt * 16 * SROW_B + kB);
                ldsm_x4(al[mt], sb + stage + ARR_B + a_off + mt * 16 * SROW_B + kB);
            }
#pragma unroll
            for (int p = 0; p < 2; p++) {
                unsigned bh[4], bl[4];
                ldsm_x4(bh, sb + SM_WH + b_off + p * 16 * SROW_B + kB);
                ldsm_x4(bl, sb + SM_WL + b_off + p * 16 * SROW_B + kB);
#pragma unroll
                for (int mt = 0; mt < 2; mt++) {
                    mma_bf16(acc[mt][2 * p],     ah[mt], bh);
                    mma_bf16(acc[mt][2 * p],     ah[mt], bl);
                    mma_bf16(acc[mt][2 * p],     al[mt], bh);
                    mma_bf16(acc[mt][2 * p + 1], ah[mt], bh + 2);
                    mma_bf16(acc[mt][2 * p + 1], ah[mt], bl + 2);
                    mma_bf16(acc[mt][2 * p + 1], al[mt], bh + 2);
                }
            }
        }
#pragma unroll
        for (int mt = 0; mt < 2; mt++)
#pragma unroll
            for (int nt = 0; nt < 4; nt++) {
                int r0 = tile * 128 + wm + mt * 16 + gid;
                int cb = wn + nt * 8 + 2 * tig;
                if (r0 < n)
                    *(float2*)(C + (size_t)r0 * CH + cb) =
                        make_float2(acc[mt][nt][0], acc[mt][nt][1]);
                if (r0 + 8 < n)
                    *(float2*)(C + (size_t)(r0 + 8) * CH + cb) =
                        make_float2(acc[mt][nt][2], acc[mt][nt][3]);
            }
    };

    if (LAYER == 1) {
        int t0 = blockIdx.x;
        if (t0 < ntiles) load_x(t0);
        CP_WAIT0();                      // W resident
        __syncthreads();
        for (int t = t0; t < ntiles; t += PGRID) {
            sts_x(SM_A0);
            __syncthreads();
            if (t + PGRID < ntiles) load_x(t + PGRID);   // overlaps compute
            compute_store(SM_A0, t);
            __syncthreads();             // stage reuse guard
        }
    } else {
        int t0 = blockIdx.x;
        if (t0 < ntiles) issue_a(t0, SM_A0);
        int s = 0;
        for (int t = t0; t < ntiles; t += PGRID) {
            CP_WAIT0();
            __syncthreads();
            if (t + PGRID < ntiles)
                issue_a(t + PGRID, SM_A0 + (s ^ 1) * 2 * ARR_B);  // overlaps compute
            compute_store(SM_A0 + s * 2 * ARR_B, t);
            s ^= 1;
        }
    }
}

// ---------------------------------------------------------------------------
// (7,9) Pull aggregation: one warp per node, register accumulation.
// SPLIT=true: relu + write bf16 hi/lo rows (feeds GEMM2).
// SPLIT=false: write fp32 rows (final output).
// ---------------------------------------------------------------------------
template <bool SPLIT>
__global__ void __launch_bounds__(256)
gather_kernel(const float* __restrict__ h, const float* __restrict__ b,
              float* __restrict__ out, int n) {
    int node = (blockIdx.x * blockDim.x + threadIdx.x) >> 5;
    int lane = threadIdx.x & 31;
    if (node >= n) return;

    int start = g_row[node];
    int deg = g_deg[node];
    float di = g_dinv[node];
    float sl = di * di;

    float4 hv = ((const float4*)(h + (size_t)node * CH))[lane];
    float4 bv = ((const float4*)b)[lane];
    float4 acc;
    acc.x = fmaf(hv.x, sl, bv.x);
    acc.y = fmaf(hv.y, sl, bv.y);
    acc.z = fmaf(hv.z, sl, bv.z);
    acc.w = fmaf(hv.w, sl, bv.w);

    for (int j0 = 0; j0 < deg; j0 += 32) {
        int nn = min(32, deg - j0);
        int2 e = make_int2(0, 0);
        if (lane < nn) e = g_csr[start + j0 + lane];
#pragma unroll 8
        for (int k = 0; k < nn; k++) {
            int s = __shfl_sync(0xFFFFFFFFu, e.x, k);
            float c = __int_as_float(__shfl_sync(0xFFFFFFFFu, e.y, k));
            float4 v = ((const float4*)(h + (size_t)s * CH))[lane];
            acc.x = fmaf(v.x, c, acc.x);
            acc.y = fmaf(v.y, c, acc.y);
            acc.z = fmaf(v.z, c, acc.z);
            acc.w = fmaf(v.w, c, acc.w);
        }
    }

    if (SPLIT) {
        float vv[4] = {fmaxf(acc.x, 0.f), fmaxf(acc.y, 0.f),
                       fmaxf(acc.z, 0.f), fmaxf(acc.w, 0.f)};
        __nv_bfloat16 hi[4], lo[4];
#pragma unroll
        for (int j = 0; j < 4; j++) {
            hi[j] = __float2bfloat16(vv[j]);
            lo[j] = __float2bfloat16(vv[j] - __bfloat162float(hi[j]));
        }
        size_t off = (size_t)node * CH + lane * 4;
        *(uint2*)(g_Ahi + off) = *(uint2*)hi;
        *(uint2*)(g_Alo + off) = *(uint2*)lo;
    } else {
        ((float4*)(out + (size_t)node * CH))[lane] = acc;
    }
}

// ---------------------------------------------------------------------------
// Launch. Slot 4 (ncu-profiled) = gemm layer 1.
// ---------------------------------------------------------------------------
extern "C" void kernel_launch(void* const* d_in, const int* in_sizes, int n_in,
                              void* d_out, int out_size) {
    const float* x  = (const float*)d_in[0];
    const void*  ei = d_in[1];
    const float* W1 = (const float*)d_in[2];
    const float* b1 = (const float*)d_in[3];
    const float* W2 = (const float*)d_in[4];
    const float* b2 = (const float*)d_in[5];
    float*       out = (float*)d_out;

    const int N = in_sizes[0] / CH;
    const int E = in_sizes[1] / 2;
    const int ntiles = (N + 127) / 128;

    float* hp = nullptr;
    cudaGetSymbolAddress((void**)&hp, g_h);

    cudaFuncSetAttribute(gemm_bf16_kernel<1>,
                         cudaFuncAttributeMaxDynamicSharedMemorySize, SMEM_L1);
    cudaFuncSetAttribute(gemm_bf16_kernel<2>,
                         cudaFuncAttributeMaxDynamicSharedMemorySize, SMEM_L2);

    const int T = 256;
    const int edge_grid = (E + T - 1) / T;
    const int node_grid = (N + T - 1) / T;
    const int conv_grid = (2 * E + T - 1) / T;
    const int warp_grid = (N * 32 + T - 1) / T;

    init_detect_kernel<<<node_grid, T>>>((const unsigned int*)ei, 2 * E, N); // 1
    convert_kernel<<<conv_grid, T>>>(ei, E);                                 // 2
    split_w_kernel<<<2, T>>>(W1, W2);                                        // 3
    gemm_bf16_kernel<1><<<PGRID, 512, SMEM_L1>>>(x, hp, N, ntiles);          // 4 (profiled)
    dinv_alloc_kernel<<<node_grid, T>>>(N);                                  // 5
    csr_fill_kernel<<<edge_grid, T>>>(E);                                    // 6
    gather_kernel<true><<<warp_grid, T>>>(hp, b1, nullptr, N);               // 7
    gemm_bf16_kernel<2><<<PGRID, 512, SMEM_L2>>>(nullptr, hp, N, ntiles);    // 8
    gather_kernel<false><<<warp_grid, T>>>(hp, b2, out, N);                  // 9
}